// round 16
// baseline (speedup 1.0000x reference)
#include <cuda_runtime.h>
#include <cuda_fp16.h>
#include <cstdint>

#define BB 2
#define NN 2048
#define DD 64
#define TI 128
#define TJ 128

// ---------------- smem layout (main kernel) ----------------
#define OFF_XN      0                      // 128 floats
#define OFF_YN      512                    // 128 floats
#define OFF_AXH     1024                   // x tile: 128 rows x 128B fp16
#define OFF_BYH     (OFF_AXH + 128 * 128)  // y tile: 128 rows x 128B fp16
#define SMEM_BYTES  (OFF_BYH + 128 * 128)  // 33792

// Precomputed fp16 panels (final smem byte layout: swizzle + y-permute baked
// in) and exact fp32 row norms.
__device__ uint32_t g_xh[BB * NN * 32];    // 64 halves per row = 128B
__device__ uint32_t g_yh[BB * NN * 32];
__device__ float g_xn[BB * NN];
__device__ float g_yn[BB * NN];

__device__ __forceinline__ uint32_t smem_u32(const void* p) {
    uint32_t a;
    asm("{ .reg .u64 t; cvta.to.shared.u64 t, %1; cvt.u32.u64 %0, t; }" : "=r"(a) : "l"(p));
    return a;
}

#define CP_ASYNC16(sa, gp) \
    asm volatile("cp.async.cg.shared.global [%0], [%1], 16;" :: "r"(sa), "l"(gp))
#define CP_ASYNC4(sa, gp) \
    asm volatile("cp.async.ca.shared.global [%0], [%1], 4;" :: "r"(sa), "l"(gp))
#define CP_COMMIT_WAIT() do { \
    asm volatile("cp.async.commit_group;"); \
    asm volatile("cp.async.wait_group 0;"); \
} while (0)

__device__ __forceinline__ void ldsm4(uint32_t* r, uint32_t addr) {
    asm volatile("ldmatrix.sync.aligned.m8n8.x4.shared.b16 {%0,%1,%2,%3}, [%4];"
        : "=r"(r[0]), "=r"(r[1]), "=r"(r[2]), "=r"(r[3]) : "r"(addr));
}

__device__ __forceinline__ void mma16816(float* c, const uint32_t* a,
                                         uint32_t b0, uint32_t b1) {
    asm volatile("mma.sync.aligned.m16n8k16.row.col.f32.f16.f16.f32 "
        "{%0,%1,%2,%3}, {%4,%5,%6,%7}, {%8,%9}, {%0,%1,%2,%3};"
        : "+f"(c[0]), "+f"(c[1]), "+f"(c[2]), "+f"(c[3])
        : "r"(a[0]), "r"(a[1]), "r"(a[2]), "r"(a[3]), "r"(b0), "r"(b1));
}

// y-row permutation (within 16-row groups): thread's 4 acc values cover 4
// consecutive logical j -> STG.128 epilogue.
// j = q*16 + w*4 + h*2 + l  ->  p = q*16 + h*8 + w*2 + l
__device__ __forceinline__ int permute_row(int j) {
    return (j & ~15) | ((j & 2) << 2) | ((j & 12) >> 1) | (j & 1);
}

// ---------------------------------------------------------------------------
// Prep: one warp per row (8192 rows). fp32 -> fp16 with swizzle (+ permute
// for y) baked into the global layout; exact fp32 norms.
// ---------------------------------------------------------------------------
__global__ __launch_bounds__(256)
void prep_kernel(const float* __restrict__ x, const float* __restrict__ y) {
    int gw = (blockIdx.x * blockDim.x + threadIdx.x) >> 5;   // 0..8191
    int lane = threadIdx.x & 31;
    bool isX = gw < BB * NN;
    int r = gw & (BB * NN - 1);
    const float* src = (isX ? x : y) + (size_t)r * DD;

    float2 v = *(const float2*)(src + 2 * lane);
    float s = v.x * v.x + v.y * v.y;
    #pragma unroll
    for (int o = 16; o; o >>= 1) s += __shfl_xor_sync(0xffffffffu, s, o);

    __half2 h = __float22half2_rn(v);
    if (isX) {
        uint32_t off = (uint32_t)(4 * lane) ^ (uint32_t)((r & 7) * 16);
        *(uint32_t*)((char*)g_xh + (size_t)r * 128 + off) = *(uint32_t*)&h;
        if (lane == 0) g_xn[r] = s;
    } else {
        int p = permute_row(r);
        uint32_t off = (uint32_t)(4 * lane) ^ (uint32_t)((p & 7) * 16);
        *(uint32_t*)((char*)g_yh + (size_t)p * 128 + off) = *(uint32_t*)&h;
        if (lane == 0) g_yn[r] = s;
    }
}

// ---------------------------------------------------------------------------
// Main: 128x128 tile per CTA. Fill = pure cp.async memcpy of pre-swizzled
// fp16 panels + norms. fp16 single-pass GEMM on HMMA.
// ---------------------------------------------------------------------------
__global__ __launch_bounds__(256, 2)
void pd_kernel(float* __restrict__ out) {
    extern __shared__ char smem[];
    uint32_t sb = smem_u32(smem);
    int tid = threadIdx.x;
    int wid = tid >> 5;
    int lane = tid & 31;
    int b = blockIdx.z;
    int i0 = blockIdx.y * TI;
    int j0 = blockIdx.x * TJ;

    float* xns_sm = (float*)(smem + OFF_XN);
    float* yns_sm = (float*)(smem + OFF_YN);

    // ---- fill: straight async memcpy (layout already final) ----
    const char* xsrc = (const char*)g_xh + (size_t)(b * NN + i0) * 128;
    const char* ysrc = (const char*)g_yh + (size_t)(b * NN + j0) * 128;
    #pragma unroll
    for (int it = 0; it < 4; it++) {
        uint32_t o = (uint32_t)tid * 16 + it * 4096;
        CP_ASYNC16(sb + OFF_AXH + o, xsrc + o);
        CP_ASYNC16(sb + OFF_BYH + o, ysrc + o);
    }
    if (tid < 128)
        CP_ASYNC4(sb + OFF_XN + tid * 4, (const char*)(g_xn + b * NN + i0) + tid * 4);
    else
        CP_ASYNC4(sb + OFF_YN + (tid - 128) * 4,
                  (const char*)(g_yn + b * NN + j0) + (tid - 128) * 4);
    CP_COMMIT_WAIT();
    __syncthreads();

    // ---- warp tiling: warp (mw, nw) -> rows mw*32..+31, cols nw*64..+63 ----
    int mw = wid & 3;
    int nw = wid >> 2;

    uint32_t rA[2], mskA[2];
    #pragma unroll
    for (int mt = 0; mt < 2; mt++) {
        uint32_t row = mw * 32 + mt * 16 + (lane & 7) + ((lane >> 3) & 1) * 8;
        rA[mt] = row * 128;
        mskA[mt] = (rA[mt] >> 3) & 0x70;
    }
    uint32_t kA = (lane >> 4) * 16;
    uint32_t rB[4], mskB[4];
    #pragma unroll
    for (int np = 0; np < 4; np++) {
        uint32_t row = nw * 64 + np * 16 + (lane & 7) + ((lane >> 4) & 1) * 8;
        rB[np] = row * 128;
        mskB[np] = (rB[np] >> 3) & 0x70;
    }
    uint32_t kB = ((lane >> 3) & 1) * 16;

    float acc[2][8][4];
    #pragma unroll
    for (int mt = 0; mt < 2; mt++)
        #pragma unroll
        for (int nt = 0; nt < 8; nt++)
            #pragma unroll
            for (int q = 0; q < 4; q++) acc[mt][nt][q] = 0.f;

    // ---- mainloop: 4 kb panels, double-buffered fragments (prefetch kb+1) ----
    uint32_t af[2][2][4], bf[2][4][4];
    #pragma unroll
    for (int mt = 0; mt < 2; mt++)
        ldsm4(af[0][mt], sb + OFF_AXH + rA[mt] + (kA ^ mskA[mt]));
    #pragma unroll
    for (int np = 0; np < 4; np++)
        ldsm4(bf[0][np], sb + OFF_BYH + rB[np] + (kB ^ mskB[np]));

    #pragma unroll
    for (int kb = 0; kb < 4; kb++) {
        int cur = kb & 1, nxt = cur ^ 1;
        if (kb < 3) {
            uint32_t kbyte = (uint32_t)(kb + 1) * 32;
            #pragma unroll
            for (int mt = 0; mt < 2; mt++)
                ldsm4(af[nxt][mt], sb + OFF_AXH + rA[mt] + ((kbyte + kA) ^ mskA[mt]));
            #pragma unroll
            for (int np = 0; np < 4; np++)
                ldsm4(bf[nxt][np], sb + OFF_BYH + rB[np] + ((kbyte + kB) ^ mskB[np]));
        }
        #pragma unroll
        for (int mt = 0; mt < 2; mt++)
            #pragma unroll
            for (int np = 0; np < 4; np++) {
                mma16816(acc[mt][2 * np],     af[cur][mt], bf[cur][np][0], bf[cur][np][1]);
                mma16816(acc[mt][2 * np + 1], af[cur][mt], bf[cur][np][2], bf[cur][np][3]);
            }
    }

    // ---- epilogue: out = xn + yn - 2*dot; permuted j -> STG.128 ----
    int g = lane >> 2;
    int tq = lane & 3;

    #pragma unroll
    for (int mt = 0; mt < 2; mt++) {
        int rlo = mw * 32 + mt * 16 + g;
        float xn_lo = xns_sm[rlo];
        float xn_hi = xns_sm[rlo + 8];
        float* out_lo = out + ((size_t)(b * NN + i0 + rlo)) * NN + j0;
        float* out_hi = out_lo + (size_t)8 * NN;
        #pragma unroll
        for (int q = 0; q < 4; q++) {
            int jl = nw * 64 + q * 16 + tq * 4;   // 4 consecutive logical j
            float4 yn = *(const float4*)(yns_sm + jl);
            float* aA = acc[mt][2 * q];       // physical block h=0 -> j+0, j+1
            float* aB = acc[mt][2 * q + 1];   // physical block h=1 -> j+2, j+3
            float4 v;
            v.x = fmaf(-2.f, aA[0], xn_lo + yn.x);
            v.y = fmaf(-2.f, aA[1], xn_lo + yn.y);
            v.z = fmaf(-2.f, aB[0], xn_lo + yn.z);
            v.w = fmaf(-2.f, aB[1], xn_lo + yn.w);
            *(float4*)(out_lo + jl) = v;
            v.x = fmaf(-2.f, aA[2], xn_hi + yn.x);
            v.y = fmaf(-2.f, aA[3], xn_hi + yn.y);
            v.z = fmaf(-2.f, aB[2], xn_hi + yn.z);
            v.w = fmaf(-2.f, aB[3], xn_hi + yn.w);
            *(float4*)(out_hi + jl) = v;
        }
    }
}

extern "C" void kernel_launch(void* const* d_in, const int* in_sizes, int n_in,
                              void* d_out, int out_size) {
    const float* x = (const float*)d_in[0];
    const float* y = (const float*)d_in[1];
    float* out = (float*)d_out;

    cudaFuncSetAttribute(pd_kernel, cudaFuncAttributeMaxDynamicSharedMemorySize,
                         (int)SMEM_BYTES);

    // 8192 warps (one per row of x then y) = 1024 CTAs
    prep_kernel<<<(2 * BB * NN * 32) / 256, 256>>>(x, y);

    dim3 grid(NN / TJ, NN / TI, BB);
    pd_kernel<<<grid, 256, SMEM_BYTES>>>(out);
}